// round 2
// baseline (speedup 1.0000x reference)
#include <cuda_runtime.h>
#include <math.h>

#define Bz 8
#define Sz 2048
#define Dz 1024
#define Nz 256
#define Hz 512
#define Ez 8
#define Tz (Bz*Sz)   // 16384 tokens

// ---------------- scratch (static device allocations, allowed) -------------
__device__ int   g_routes[Tz];
__device__ int   g_cnt[Ez];
__device__ int   g_off[Ez+1];
__device__ int   g_cur[Ez];
__device__ int   g_tok[Tz];
__device__ float g_u [(size_t)Tz*Nz];
__device__ float g_sh[(size_t)Tz*Hz];
__device__ float g_a [(size_t)Tz*Nz];
__device__ float g_bu[(size_t)Tz*Nz];
__device__ float g_c [(size_t)Tz*Nz];
__device__ float g_sk[(size_t)Tz*Nz];
__device__ float g_y [(size_t)Tz*Nz];

__device__ __forceinline__ float sigf(float v){ return 1.0f/(1.0f + expf(-v)); }

// ---------------- routing / counting sort ----------------------------------
__global__ void k_zero(){
    int t = threadIdx.x;
    if (t < Ez){ g_cnt[t] = 0; g_cur[t] = 0; }
}

__global__ void k_route(const int* __restrict__ tid){
    int t = blockIdx.x*256 + threadIdx.x;
    if (t >= Tz) return;
    unsigned x = (unsigned)tid[t];
    x ^= x >> 16; x *= 2246822507u;
    x ^= x >> 13; x *= 3266489909u;
    x ^= x >> 16;
    int r = (int)(x & (unsigned)(Ez-1));
    g_routes[t] = r;
    atomicAdd(&g_cnt[r], 1);
}

__global__ void k_off(){
    int s = 0;
    for (int e = 0; e < Ez; e++){ g_off[e] = s; s += g_cnt[e]; }
    g_off[Ez] = s;
}

__global__ void k_scatter(){
    int t = blockIdx.x*256 + threadIdx.x;
    if (t >= Tz) return;
    int r = g_routes[t];
    int pos = g_off[r] + atomicAdd(&g_cur[r], 1);
    g_tok[pos] = t;
}

// ---------------- grouped GEMM: 128x64 tile, BK=16, 256 threads ------------
// STAGE 0: A = x (K=1024), W = [Win | Wsin], epilogue -> g_u / silu -> g_sh
// STAGE 1: A = g_sh (K=512), W = Wsout,     epilogue -> g_a,g_bu,g_c,g_sk
// STAGE 2: A = g_y (K=256),  W = Wout,      epilogue -> d_out
template<int STAGE>
__global__ void __launch_bounds__(256,2)
k_gemm(const float* __restrict__ Xin,
       const float* __restrict__ Wa,
       const float* __restrict__ Wb,
       const float* __restrict__ dpar,
       float* __restrict__ outp)
{
    constexpr int KD = (STAGE==0) ? Dz : (STAGE==1) ? Hz : Nz;
    const int e   = blockIdx.z;
    const int cnt = g_cnt[e];
    const int mt  = blockIdx.y;
    if (mt*128 >= cnt) return;
    const int off  = g_off[e];
    const int col0 = blockIdx.x * 64;

    const float* Asrc;
    if (STAGE==0)      Asrc = Xin;
    else if (STAGE==1) Asrc = g_sh;
    else               Asrc = g_y;

    const float* Wbase;
    if (STAGE==0){
        Wbase = (col0 < Nz) ? (Wa + ((size_t)e*Nz + col0)*(size_t)KD)
                            : (Wb + ((size_t)e*Hz + (col0-Nz))*(size_t)KD);
    } else if (STAGE==1){
        Wbase = Wa + ((size_t)e*(4*Nz) + col0)*(size_t)KD;
    } else {
        Wbase = Wa + ((size_t)e*Dz + col0)*(size_t)KD;
    }

    __shared__ float As[16][128];
    __shared__ float Bs[16][64];
    __shared__ int   s_tok[128];

    const int t = threadIdx.x;
    if (t < 128){
        int i = mt*128 + t;
        s_tok[t] = (i < cnt) ? g_tok[off + i] : -1;
    }
    __syncthreads();

    const int q4  = (t & 3) * 4;     // k-quad within 16
    const int rA0 = t >> 2;          // 0..63
    const int rA1 = rA0 + 64;        // 64..127
    const int tok0 = s_tok[rA0];
    const int tok1 = s_tok[rA1];
    const size_t a0row = (size_t)(tok0 < 0 ? 0 : tok0) * KD + q4;
    const size_t a1row = (size_t)(tok1 < 0 ? 0 : tok1) * KD + q4;
    const size_t brow  = (size_t)rA0 * KD + q4;

    const float4 z4 = make_float4(0.f,0.f,0.f,0.f);
    float4 pa0 = (tok0 >= 0) ? *(const float4*)(Asrc + a0row) : z4;
    float4 pa1 = (tok1 >= 0) ? *(const float4*)(Asrc + a1row) : z4;
    float4 pb  = *(const float4*)(Wbase + brow);

    float acc[8][4];
    #pragma unroll
    for (int i = 0; i < 8; i++)
        #pragma unroll
        for (int j = 0; j < 4; j++) acc[i][j] = 0.f;

    const int ty = t >> 4;   // 0..15 -> rows ty*8..ty*8+7
    const int tx = t & 15;   // 0..15 -> cols tx*4..tx*4+3

    for (int k0 = 0; k0 < KD; k0 += 16){
        #pragma unroll
        for (int j = 0; j < 4; j++){
            As[q4 + j][rA0] = (&pa0.x)[j];
            As[q4 + j][rA1] = (&pa1.x)[j];
            Bs[q4 + j][rA0] = (&pb.x)[j];
        }
        __syncthreads();
        const int kn = k0 + 16;
        if (kn < KD){
            pa0 = (tok0 >= 0) ? *(const float4*)(Asrc + a0row + kn) : z4;
            pa1 = (tok1 >= 0) ? *(const float4*)(Asrc + a1row + kn) : z4;
            pb  = *(const float4*)(Wbase + brow + kn);
        }
        #pragma unroll
        for (int kk = 0; kk < 16; kk++){
            float4 av0 = *(const float4*)&As[kk][ty*8];
            float4 av1 = *(const float4*)&As[kk][ty*8 + 4];
            float4 bv  = *(const float4*)&Bs[kk][tx*4];
            float aa[8] = {av0.x,av0.y,av0.z,av0.w, av1.x,av1.y,av1.z,av1.w};
            float bb[4] = {bv.x,bv.y,bv.z,bv.w};
            #pragma unroll
            for (int i = 0; i < 8; i++)
                #pragma unroll
                for (int j = 0; j < 4; j++)
                    acc[i][j] = fmaf(aa[i], bb[j], acc[i][j]);
        }
        __syncthreads();
    }

    // -------- epilogue --------
    float4 dp4 = z4;
    if (STAGE==1 && (col0 >> 8) == 3){
        dp4 = *(const float4*)(dpar + (size_t)e*Nz + (col0 & 255) + tx*4);
    }

    #pragma unroll
    for (int i = 0; i < 8; i++){
        int tokr = s_tok[ty*8 + i];
        if (tokr < 0) continue;
        float v0 = acc[i][0], v1 = acc[i][1], v2 = acc[i][2], v3 = acc[i][3];
        if (STAGE==0){
            if (col0 < Nz){
                *(float4*)(g_u + (size_t)tokr*Nz + col0 + tx*4) =
                    make_float4(v0, v1, v2, v3);
            } else {
                *(float4*)(g_sh + (size_t)tokr*Hz + (col0 - Nz) + tx*4) =
                    make_float4(v0*sigf(v0), v1*sigf(v1), v2*sigf(v2), v3*sigf(v3));
            }
        } else if (STAGE==1){
            const int q  = col0 >> 8;          // quarter of selector output
            const int n0 = (col0 & 255) + tx*4;
            size_t p = (size_t)tokr*Nz + n0;
            if (q == 0){
                *(float4*)(g_a + p) = make_float4(sigf(v0), sigf(v1), sigf(v2), sigf(v3));
            } else if (q == 1){
                float4 u4 = *(const float4*)(g_u + p);
                *(float4*)(g_bu + p) = make_float4(tanhf(v0)*u4.x, tanhf(v1)*u4.y,
                                                   tanhf(v2)*u4.z, tanhf(v3)*u4.w);
            } else if (q == 2){
                *(float4*)(g_c + p) = make_float4(tanhf(v0), tanhf(v1), tanhf(v2), tanhf(v3));
            } else {
                float4 u4 = *(const float4*)(g_u + p);
                *(float4*)(g_sk + p) = make_float4(dp4.x*sigf(v0)*u4.x, dp4.y*sigf(v1)*u4.y,
                                                   dp4.z*sigf(v2)*u4.z, dp4.w*sigf(v3)*u4.w);
            }
        } else {
            *(float4*)(outp + (size_t)tokr*Dz + col0 + tx*4) =
                make_float4(v0, v1, v2, v3);
        }
    }
}

// ---------------- sequential scan: thread per (b,n) channel ----------------
struct Grp { float a[8], bu[8], c[8], sk[8]; int r[8]; };

__device__ __forceinline__ void load_grp(Grp& g, size_t base, int brow, int s0){
    #pragma unroll
    for (int i = 0; i < 8; i++){
        size_t p = base + (size_t)(s0 + i) * Nz;
        g.a[i]  = g_a [p];
        g.bu[i] = g_bu[p];
        g.c[i]  = g_c [p];
        g.sk[i] = g_sk[p];
        g.r[i]  = g_routes[brow + s0 + i];
    }
}

__device__ __forceinline__ void comp_grp(const Grp& g, size_t base, int s0, float h[Ez]){
    #pragma unroll
    for (int i = 0; i < 8; i++){
        int r = g.r[i];
        float hp = 0.f;
        #pragma unroll
        for (int e = 0; e < Ez; e++) if (r == e) hp = h[e];
        float hn = fmaf(g.a[i], hp, g.bu[i]);
        #pragma unroll
        for (int e = 0; e < Ez; e++) if (r == e) h[e] = hn;
        g_y[base + (size_t)(s0 + i) * Nz] = fmaf(g.c[i], hn, g.sk[i]);
    }
}

__global__ void k_scan(){
    const int b = blockIdx.x;
    const int n = blockIdx.y * 64 + threadIdx.x;
    const int brow = b * Sz;
    const size_t base = (size_t)brow * Nz + n;
    float h[Ez];
    #pragma unroll
    for (int e = 0; e < Ez; e++) h[e] = 0.f;

    Grp g0, g1;
    load_grp(g0, base, brow, 0);
    for (int s0 = 0; s0 < Sz; s0 += 16){
        load_grp(g1, base, brow, s0 + 8);
        comp_grp(g0, base, s0, h);
        if (s0 + 16 < Sz) load_grp(g0, base, brow, s0 + 16);
        comp_grp(g1, base, s0 + 8, h);
    }
}

// ---------------- launch ----------------------------------------------------
extern "C" void kernel_launch(void* const* d_in, const int* in_sizes, int n_in,
                              void* d_out, int out_size){
    const float* x     = (const float*)d_in[0];
    const int*   tid   = (const int*)  d_in[1];
    const float* Win   = (const float*)d_in[2];
    const float* Wsin  = (const float*)d_in[3];
    const float* Wsout = (const float*)d_in[4];
    const float* Wout  = (const float*)d_in[5];
    const float* dpar  = (const float*)d_in[6];
    float* out = (float*)d_out;

    k_zero   <<<1, 32>>>();
    k_route  <<<Tz/256, 256>>>(tid);
    k_off    <<<1, 1>>>();
    k_scatter<<<Tz/256, 256>>>();

    // fused in_proj + selector_in (768 output cols), K = 1024
    k_gemm<0><<<dim3(768/64,  Tz/128, Ez), 256>>>(x, Win, Wsin, nullptr, nullptr);
    // selector_out (1024 cols), K = 512, fused activations + u/skip combine
    k_gemm<1><<<dim3(1024/64, Tz/128, Ez), 256>>>(nullptr, Wsout, nullptr, dpar, nullptr);
    // sequential SSM scan
    k_scan   <<<dim3(Bz, 4), 64>>>();
    // out_proj (1024 cols), K = 256
    k_gemm<2><<<dim3(1024/64, Tz/128, Ez), 256>>>(nullptr, Wout, nullptr, nullptr, out);
}

// round 7
// speedup vs baseline: 1.8811x; 1.8811x over previous
#include <cuda_runtime.h>
#include <cuda_bf16.h>
#include <cstdint>
#include <math.h>

#define Bz 8
#define Sz 2048
#define Dz 1024
#define Nz 256
#define Hz 512
#define Ez 8
#define Tz (Bz*Sz)   // 16384 tokens

typedef unsigned int uint;
typedef unsigned short ushort;

// ---------------- scratch (static device allocations, allowed) -------------
__device__ int   g_routes[Tz];
__device__ int   g_cnt[Ez];
__device__ int   g_off[Ez+1];
__device__ int   g_cur[Ez];
__device__ int   g_tok[Tz];

__device__ float g_u [(size_t)Tz*Nz];
__device__ float g_a [(size_t)Tz*Nz];
__device__ float g_bu[(size_t)Tz*Nz];
__device__ float g_c [(size_t)Tz*Nz];
__device__ float g_sk[(size_t)Tz*Nz];

// split-bf16 operand buffers
__device__ ushort g_xb [(size_t)Tz*Dz];
__device__ ushort g_xs [(size_t)Tz*Dz];
__device__ ushort g_shb[(size_t)Tz*Hz];
__device__ ushort g_shs[(size_t)Tz*Hz];
__device__ ushort g_yb [(size_t)Tz*Nz];
__device__ ushort g_ys [(size_t)Tz*Nz];
__device__ ushort g_winb [(size_t)Ez*Nz*Dz];
__device__ ushort g_wins [(size_t)Ez*Nz*Dz];
__device__ ushort g_wsinb[(size_t)Ez*Hz*Dz];
__device__ ushort g_wsins[(size_t)Ez*Hz*Dz];
__device__ ushort g_wsoutb[(size_t)Ez*4*Nz*Hz];
__device__ ushort g_wsouts[(size_t)Ez*4*Nz*Hz];
__device__ ushort g_woutb[(size_t)Ez*Dz*Nz];
__device__ ushort g_wouts[(size_t)Ez*Dz*Nz];

// ---------------- helpers ----------------------------------------------------
__device__ __forceinline__ uint32_t smem_u32(const void* p){
    uint32_t a;
    asm("{ .reg .u64 t; cvta.to.shared.u64 t, %1; cvt.u32.u64 %0, t; }" : "=r"(a) : "l"(p));
    return a;
}
__device__ __forceinline__ float tanh_fast(float x){
    float r; asm("tanh.approx.f32 %0, %1;" : "=f"(r) : "f"(x)); return r;
}
__device__ __forceinline__ float sig_fast(float x){ return fmaf(0.5f, tanh_fast(0.5f*x), 0.5f); }

__device__ __forceinline__ uint bf2(float lo, float hi){
    uint r; asm("cvt.rn.bf16x2.f32 %0, %1, %2;" : "=r"(r) : "f"(hi), "f"(lo)); return r;
}
__device__ __forceinline__ uint32_t sw128(uint32_t o){ return o ^ ((o>>3)&0x70); }

#define CP16(dst, src, sz) \
    asm volatile("cp.async.cg.shared.global [%0], [%1], 16, %2;" \
                 :: "r"(dst), "l"(src), "r"(sz) : "memory")
#define CP_COMMIT() asm volatile("cp.async.commit_group;" ::: "memory")
template<int N> __device__ __forceinline__ void cp_wait(){
    asm volatile("cp.async.wait_group %0;" :: "n"(N) : "memory");
}
#define LDSM4(r, addr) \
    asm volatile("ldmatrix.sync.aligned.m8n8.x4.shared.b16 {%0,%1,%2,%3}, [%4];" \
                 : "=r"((r)[0]),"=r"((r)[1]),"=r"((r)[2]),"=r"((r)[3]) : "r"(addr))
#define MMA(d, a, b0_, b1_) \
    asm volatile("mma.sync.aligned.m16n8k16.row.col.f32.bf16.bf16.f32 " \
                 "{%0,%1,%2,%3},{%4,%5,%6,%7},{%8,%9},{%0,%1,%2,%3};" \
                 : "+f"((d)[0]),"+f"((d)[1]),"+f"((d)[2]),"+f"((d)[3]) \
                 : "r"((a)[0]),"r"((a)[1]),"r"((a)[2]),"r"((a)[3]), "r"(b0_),"r"(b1_))

// ---------------- fp32 -> split bf16 conversion ------------------------------
__global__ void k_split(const float* __restrict__ src, ushort* __restrict__ db,
                        ushort* __restrict__ ds, int n4){
    int i = blockIdx.x*blockDim.x + threadIdx.x;
    int stride = gridDim.x*blockDim.x;
    for (; i < n4; i += stride){
        float4 v = ((const float4*)src)[i];
        uint b0=__float_as_uint(v.x), b1=__float_as_uint(v.y),
             b2=__float_as_uint(v.z), b3=__float_as_uint(v.w);
        uint2 big;
        big.x = __byte_perm(b0,b1,0x7632);
        big.y = __byte_perm(b2,b3,0x7632);
        float s0 = v.x - __uint_as_float(b0 & 0xffff0000u);
        float s1 = v.y - __uint_as_float(b1 & 0xffff0000u);
        float s2 = v.z - __uint_as_float(b2 & 0xffff0000u);
        float s3 = v.w - __uint_as_float(b3 & 0xffff0000u);
        uint2 sml; sml.x = bf2(s0,s1); sml.y = bf2(s2,s3);
        ((uint2*)db)[i] = big;
        ((uint2*)ds)[i] = sml;
    }
}

// ---------------- routing / counting sort ------------------------------------
__global__ void k_zero(){
    int t = threadIdx.x;
    if (t < Ez){ g_cnt[t] = 0; g_cur[t] = 0; }
}
__global__ void k_route(const int* __restrict__ tid){
    int t = blockIdx.x*256 + threadIdx.x;
    if (t >= Tz) return;
    unsigned x = (unsigned)tid[t];
    x ^= x >> 16; x *= 2246822507u;
    x ^= x >> 13; x *= 3266489909u;
    x ^= x >> 16;
    int r = (int)(x & (unsigned)(Ez-1));
    g_routes[t] = r;
    atomicAdd(&g_cnt[r], 1);
}
__global__ void k_off(){
    int s = 0;
    for (int e = 0; e < Ez; e++){ g_off[e] = s; s += g_cnt[e]; }
    g_off[Ez] = s;
}
__global__ void k_scatter(){
    int t = blockIdx.x*256 + threadIdx.x;
    if (t >= Tz) return;
    int r = g_routes[t];
    int pos = g_off[r] + atomicAdd(&g_cur[r], 1);
    g_tok[pos] = t;
}

// ---------------- HMMA grouped GEMM ------------------------------------------
// CTA tile: 128 tokens x 64 cols, BK=64, 8 warps (4x2, warp tile 32x32).
// 3-pass bf16 split: Ab*Bb + Ab*Bs + As*Bb, fp32 accumulate.
// SMEM per buffer: Abig 16K | Asmall 16K | Bbig 8K | Bsmall 8K (SW128 rows of 128B)
#define SM_BUF     1024
#define OFF_AS     16384
#define OFF_BB     32768
#define OFF_BS     40960
#define BUF_STRIDE 49152
#define SMEM_BYTES (SM_BUF + 2*BUF_STRIDE)

template<int STAGE>
__global__ void __launch_bounds__(256,2)
k_gemm(const float* __restrict__ dpar, float* __restrict__ outp)
{
    constexpr int KD = (STAGE==0) ? Dz : (STAGE==1) ? Hz : Nz;
    constexpr int NS = KD / 64;

    const int e   = blockIdx.z;
    const int cnt = g_cnt[e];
    const int mt  = blockIdx.y;
    if (mt*128 >= cnt) return;
    const int off  = g_off[e];
    const int col0 = blockIdx.x * 64;

    const ushort* Ab = (STAGE==0) ? g_xb : (STAGE==1) ? g_shb : g_yb;
    const ushort* As = (STAGE==0) ? g_xs : (STAGE==1) ? g_shs : g_ys;
    const ushort *Wbp, *Wsp;
    if (STAGE==0){
        if (col0 < Nz){
            Wbp = g_winb + ((size_t)e*Nz + col0)*(size_t)KD;
            Wsp = g_wins + ((size_t)e*Nz + col0)*(size_t)KD;
        } else {
            Wbp = g_wsinb + ((size_t)e*Hz + (col0-Nz))*(size_t)KD;
            Wsp = g_wsins + ((size_t)e*Hz + (col0-Nz))*(size_t)KD;
        }
    } else if (STAGE==1){
        Wbp = g_wsoutb + ((size_t)e*(4*Nz) + col0)*(size_t)KD;
        Wsp = g_wsouts + ((size_t)e*(4*Nz) + col0)*(size_t)KD;
    } else {
        Wbp = g_woutb + ((size_t)e*Dz + col0)*(size_t)KD;
        Wsp = g_wouts + ((size_t)e*Dz + col0)*(size_t)KD;
    }

    extern __shared__ char smem[];
    int* s_tok = (int*)smem;
    const uint32_t sb = smem_u32(smem);
    const int t = threadIdx.x, wid = t >> 5, lid = t & 31;

    if (t < 128){
        int i = mt*128 + t;
        s_tok[t] = (i < cnt) ? g_tok[off + i] : -1;
    }
    __syncthreads();

    // ---- cp.async addressing (fixed per thread) ----
    const int seg = t & 7;     // 16B segment within 128B row
    const int r0  = t >> 3;    // 0..31
    uint32_t dA[4]; uint32_t szA[4]; size_t iA[4];
    #pragma unroll
    for (int i = 0; i < 4; i++){
        int row = r0 + 32*i;             // 0..127
        int tok = s_tok[row];
        dA[i]  = sw128((uint32_t)(row*128 + seg*16));
        szA[i] = (tok >= 0) ? 16u : 0u;
        iA[i]  = (size_t)(tok >= 0 ? tok : 0) * KD + seg*8;
    }
    uint32_t dB[2]; size_t iB[2];
    #pragma unroll
    for (int i = 0; i < 2; i++){
        int row = r0 + 32*i;             // 0..63
        dB[i] = sw128((uint32_t)(row*128 + seg*16));
        iB[i] = (size_t)row * KD + seg*8;
    }

    auto stage_cp = [&](int k, uint32_t bufb){
        const int ko = k*64;
        #pragma unroll
        for (int i = 0; i < 4; i++){
            CP16(bufb + dA[i],          Ab + iA[i] + ko, szA[i]);
            CP16(bufb + OFF_AS + dA[i], As + iA[i] + ko, szA[i]);
        }
        #pragma unroll
        for (int i = 0; i < 2; i++){
            CP16(bufb + OFF_BB + dB[i], Wbp + iB[i] + ko, 16u);
            CP16(bufb + OFF_BS + dB[i], Wsp + iB[i] + ko, 16u);
        }
    };

    // ---- ldmatrix addressing ----
    const int wr = wid & 3, wc = wid >> 2;
    const int lrow = lid & 15;
    const uint32_t kl = (uint32_t)((lid >> 4) * 16);  // byte offset for k half
    uint32_t aoff[2], axor[2], boff[2], bxor[2];
    #pragma unroll
    for (int m = 0; m < 2; m++){
        int row = wr*32 + m*16 + lrow;
        aoff[m] = (uint32_t)(row*128);
        axor[m] = (uint32_t)((row & 7) << 4);
    }
    #pragma unroll
    for (int nt = 0; nt < 2; nt++){
        int row = wc*32 + nt*16 + lrow;
        boff[nt] = (uint32_t)(row*128);
        bxor[nt] = (uint32_t)((row & 7) << 4);
    }

    float acc[2][4][4];
    #pragma unroll
    for (int m = 0; m < 2; m++)
        #pragma unroll
        for (int nb = 0; nb < 4; nb++)
            #pragma unroll
            for (int j = 0; j < 4; j++) acc[m][nb][j] = 0.f;

    // prologue
    stage_cp(0, sb + SM_BUF);
    CP_COMMIT();

    for (int k = 0; k < NS; k++){
        if (k + 1 < NS){
            stage_cp(k+1, sb + SM_BUF + (uint32_t)((k+1)&1)*BUF_STRIDE);
            CP_COMMIT();
            cp_wait<1>();
        } else {
            cp_wait<0>();
        }
        __syncthreads();
        const uint32_t bb = sb + SM_BUF + (uint32_t)(k&1)*BUF_STRIDE;
        #pragma unroll
        for (int ks = 0; ks < 4; ks++){
            const uint32_t kb = (uint32_t)(ks*32) + kl;
            uint32_t Abf[2][4], Asf[2][4], Bbf[2][4], Bsf[2][4];
            #pragma unroll
            for (int m = 0; m < 2; m++){
                uint32_t ad = bb + aoff[m] + (kb ^ axor[m]);
                LDSM4(Abf[m], ad);
                LDSM4(Asf[m], ad + OFF_AS);
            }
            #pragma unroll
            for (int nt = 0; nt < 2; nt++){
                uint32_t bd = bb + OFF_BB + boff[nt] + (kb ^ bxor[nt]);
                LDSM4(Bbf[nt], bd);
                LDSM4(Bsf[nt], bd + (OFF_BS - OFF_BB));
            }
            #pragma unroll
            for (int m = 0; m < 2; m++)
                #pragma unroll
                for (int nb = 0; nb < 4; nb++){
                    const int nt = nb >> 1, p = nb & 1;
                    MMA(acc[m][nb], Abf[m], Bbf[nt][p], Bbf[nt][p+2]);
                    MMA(acc[m][nb], Abf[m], Bsf[nt][p], Bsf[nt][p+2]);
                    MMA(acc[m][nb], Asf[m], Bbf[nt][p], Bbf[nt][p+2]);
                }
        }
        __syncthreads();
    }

    // ---- epilogue ----
    const int er = lid >> 2;
    const int ec = (lid & 3) * 2;
    #pragma unroll
    for (int m = 0; m < 2; m++){
        #pragma unroll
        for (int h = 0; h < 2; h++){
            const int row = wr*32 + m*16 + h*8 + er;
            const int tok = s_tok[row];
            if (tok < 0) continue;
            float v[8];
            #pragma unroll
            for (int nb = 0; nb < 4; nb++){
                v[2*nb]   = acc[m][nb][2*h];
                v[2*nb+1] = acc[m][nb][2*h+1];
            }
            const int cb = wc*32 + ec;   // col within 64-wide tile

            if (STAGE == 0){
                if (col0 < Nz){
                    float* dst = g_u + (size_t)tok*Nz + col0 + cb;
                    #pragma unroll
                    for (int nb = 0; nb < 4; nb++)
                        *(float2*)(dst + nb*8) = make_float2(v[2*nb], v[2*nb+1]);
                } else {
                    const size_t base = (size_t)tok*Hz + (col0 - Nz) + cb;
                    #pragma unroll
                    for (int nb = 0; nb < 4; nb++){
                        float s0 = v[2*nb]   * sig_fast(v[2*nb]);
                        float s1 = v[2*nb+1] * sig_fast(v[2*nb+1]);
                        uint u0 = __float_as_uint(s0), u1 = __float_as_uint(s1);
                        *(uint*)(g_shb + base + nb*8) = __byte_perm(u0, u1, 0x7632);
                        float r0s = s0 - __uint_as_float(u0 & 0xffff0000u);
                        float r1s = s1 - __uint_as_float(u1 & 0xffff0000u);
                        *(uint*)(g_shs + base + nb*8) = bf2(r0s, r1s);
                    }
                }
            } else if (STAGE == 1){
                const int q  = col0 >> 8;
                const int n0 = (col0 & 255) + cb;
                const size_t p = (size_t)tok*Nz + n0;
                if (q == 0){
                    #pragma unroll
                    for (int nb = 0; nb < 4; nb++)
                        *(float2*)(g_a + p + nb*8) =
                            make_float2(sig_fast(v[2*nb]), sig_fast(v[2*nb+1]));
                } else if (q == 1){
                    #pragma unroll
                    for (int nb = 0; nb < 4; nb++){
                        float2 u2 = *(const float2*)(g_u + p + nb*8);
                        *(float2*)(g_bu + p + nb*8) =
                            make_float2(tanh_fast(v[2*nb])*u2.x, tanh_fast(v[2*nb+1])*u2.y);
                    }
                } else if (q == 2){
                    #pragma unroll
                    for (int nb = 0; nb < 4; nb++)
                        *(float2*)(g_c + p + nb*8) =
                            make_float2(tanh_fast(v[2*nb]), tanh_fast(v[2*nb+1]));
                } else {
                    #pragma unroll
                    for (int nb = 0; nb < 4; nb++){
                        float2 u2 = *(const float2*)(g_u + p + nb*8);
                        float2 d2 = *(const float2*)(dpar + (size_t)e*Nz + n0 + nb*8);
                        *(float2*)(g_sk + p + nb*8) =
                            make_float2(d2.x*sig_fast(v[2*nb])*u2.x,
                                        d2.y*sig_fast(v[2*nb+1])*u2.y);
                    }
                }
            } else {
                float* dst = outp + (size_t)tok*Dz + col0 + cb;
                #pragma unroll
                for (int nb = 0; nb < 4; nb++)
                    *(float2*)(dst + nb*8) = make_float2(v[2*nb], v[2*nb+1]);
            }
        }
    }
}

// ---------------- sequential scan: thread per (b,n) channel ------------------
struct Grp { float a[8], bu[8], c[8], sk[8]; int r[8]; };

__device__ __forceinline__ void load_grp(Grp& g, size_t base, int brow, int s0){
    #pragma unroll
    for (int i = 0; i < 8; i++){
        size_t p = base + (size_t)(s0 + i) * Nz;
        g.a[i]  = g_a [p];
        g.bu[i] = g_bu[p];
        g.c[i]  = g_c [p];
        g.sk[i] = g_sk[p];
        g.r[i]  = g_routes[brow + s0 + i];
    }
}
__device__ __forceinline__ void comp_grp(const Grp& g, size_t base, int s0, float h[Ez]){
    #pragma unroll
    for (int i = 0; i < 8; i++){
        int r = g.r[i];
        float hp = 0.f;
        #pragma unroll
        for (int e = 0; e < Ez; e++) if (r == e) hp = h[e];
        float hn = fmaf(g.a[i], hp, g.bu[i]);
        #pragma unroll
        for (int e = 0; e < Ez; e++) if (r == e) h[e] = hn;
        float yv = fmaf(g.c[i], hn, g.sk[i]);
        size_t p = base + (size_t)(s0 + i) * Nz;
        uint bits = __float_as_uint(yv);
        g_yb[p] = (ushort)(bits >> 16);
        float sm = yv - __uint_as_float(bits & 0xffff0000u);
        g_ys[p] = (ushort)(bf2(sm, sm) & 0xffffu);
    }
}
__global__ void k_scan(){
    const int b = blockIdx.x;
    const int n = blockIdx.y * 64 + threadIdx.x;
    const int brow = b * Sz;
    const size_t base = (size_t)brow * Nz + n;
    float h[Ez];
    #pragma unroll
    for (int e = 0; e < Ez; e++) h[e] = 0.f;

    Grp g0, g1;
    load_grp(g0, base, brow, 0);
    for (int s0 = 0; s0 < Sz; s0 += 16){
        load_grp(g1, base, brow, s0 + 8);
        comp_grp(g0, base, s0, h);
        if (s0 + 16 < Sz) load_grp(g0, base, brow, s0 + 16);
        comp_grp(g1, base, s0 + 8, h);
    }
}

// ---------------- launch ------------------------------------------------------
extern "C" void kernel_launch(void* const* d_in, const int* in_sizes, int n_in,
                              void* d_out, int out_size){
    const float* x     = (const float*)d_in[0];
    const int*   tid   = (const int*)  d_in[1];
    const float* Win   = (const float*)d_in[2];
    const float* Wsin  = (const float*)d_in[3];
    const float* Wsout = (const float*)d_in[4];
    const float* Wout  = (const float*)d_in[5];
    const float* dpar  = (const float*)d_in[6];
    float* out = (float*)d_out;

    cudaFuncSetAttribute((const void*)k_gemm<0>, cudaFuncAttributeMaxDynamicSharedMemorySize, SMEM_BYTES);
    cudaFuncSetAttribute((const void*)k_gemm<1>, cudaFuncAttributeMaxDynamicSharedMemorySize, SMEM_BYTES);
    cudaFuncSetAttribute((const void*)k_gemm<2>, cudaFuncAttributeMaxDynamicSharedMemorySize, SMEM_BYTES);

    // resolve device-symbol addresses (host side, graph-capturable: no allocs)
    ushort *xb, *xs, *winb, *wins, *wsinb, *wsins, *wsoutb, *wsouts, *woutb, *wouts;
    cudaGetSymbolAddress((void**)&xb,     g_xb);
    cudaGetSymbolAddress((void**)&xs,     g_xs);
    cudaGetSymbolAddress((void**)&winb,   g_winb);
    cudaGetSymbolAddress((void**)&wins,   g_wins);
    cudaGetSymbolAddress((void**)&wsinb,  g_wsinb);
    cudaGetSymbolAddress((void**)&wsins,  g_wsins);
    cudaGetSymbolAddress((void**)&wsoutb, g_wsoutb);
    cudaGetSymbolAddress((void**)&wsouts, g_wsouts);
    cudaGetSymbolAddress((void**)&woutb,  g_woutb);
    cudaGetSymbolAddress((void**)&wouts,  g_wouts);

    // one-shot fp32 -> split-bf16 conversions
    k_split<<<2048, 256>>>(x,     xb,     xs,     (int)((size_t)Tz*Dz/4));
    k_split<<<512,  256>>>(Win,   winb,   wins,   (int)((size_t)Ez*Nz*Dz/4));
    k_split<<<1024, 256>>>(Wsin,  wsinb,  wsins,  (int)((size_t)Ez*Hz*Dz/4));
    k_split<<<1024, 256>>>(Wsout, wsoutb, wsouts, (int)((size_t)Ez*4*Nz*Hz/4));
    k_split<<<512,  256>>>(Wout,  woutb,  wouts,  (int)((size_t)Ez*Dz*Nz/4));

    // routing
    k_zero   <<<1, 32>>>();
    k_route  <<<Tz/256, 256>>>(tid);
    k_off    <<<1, 1>>>();
    k_scatter<<<Tz/256, 256>>>();

    // stage 0: fused in_proj + selector_in (768 cols), K = 1024
    k_gemm<0><<<dim3(768/64,  Tz/128, Ez), 256, SMEM_BYTES>>>(dpar, nullptr);
    // stage 1: selector_out (1024 cols), K = 512, fused activations
    k_gemm<1><<<dim3(1024/64, Tz/128, Ez), 256, SMEM_BYTES>>>(dpar, nullptr);
    // sequential SSM scan (writes split y)
    k_scan   <<<dim3(Bz, 4), 64>>>();
    // stage 2: out_proj (1024 cols), K = 256
    k_gemm<2><<<dim3(1024/64, Tz/128, Ez), 256, SMEM_BYTES>>>(dpar, out);
}